// round 16
// baseline (speedup 1.0000x reference)
#include <cuda_runtime.h>
#include <cstdint>

#define Bz    32
#define Hd    512
#define Tt    1000
#define G4    2048
#define NBLK  128
#define NTHR  512         // 16 warps -> 4 per SMSP
#define NW    16
#define KCH   32          // K per warp slice (512 / 16)
#define US    68          // u_sh row stride (floats): 16B-aligned float4, low conflicts
#define PS2   14          // part row stride (floats): u64-aligned
#define NCTR2 64          // counters: (bg, pair-of-rg-blocks)
#define PER_RUN 2002ull   // per-counter: 2 blocks * (1 + Tt)

// h exchange: [parity][batch-group][k][8 batches] — consumer chunks are dense 1KB.
__device__ float g_hbuf2[2][4][Hd][8];
// 64 monotone u64 arrival counters, 128B apart.
// Counter bg*16+g <- arrivals from blocks (bg, 2g..2g+2) = producers of k rows [32g,32g+32).
__device__ __align__(128) unsigned long long g_ctr[NCTR2 * 16];

__device__ __forceinline__ unsigned long long ld_acquire_u64(const unsigned long long* p) {
    unsigned long long v;
    asm volatile("ld.acquire.gpu.global.u64 %0, [%1];" : "=l"(v) : "l"(p) : "memory");
    return v;
}
__device__ __forceinline__ void red_add_release_u64(unsigned long long* p) {
    asm volatile("red.add.release.gpu.global.u64 [%0], %1;" :: "l"(p), "l"(1ull) : "memory");
}

#define FFMA2(d, a, b) asm("fma.rn.f32x2 %0, %1, %2, %0;" : "+l"(d) : "l"(a), "l"(b))
#define DUP2(d, x) asm("mov.b64 %0, {%1, %1};" : "=l"(d) : "r"(__float_as_uint(x)))

__device__ __forceinline__ float sigf(float x) {
    return __fdividef(1.0f, 1.0f + __expf(-x));
}
__device__ __forceinline__ float tanhf_fast(float x) {
    float e = __expf(2.0f * x);
    return 1.0f - __fdividef(2.0f, e + 1.0f);
}

__global__ void __launch_bounds__(NTHR, 1)
lstm_persistent(const float* __restrict__ wx, const float* __restrict__ u,
                const float* __restrict__ ub, const float* __restrict__ h0,
                const float* __restrict__ c0, float* __restrict__ out)
{
    extern __shared__ float sm[];
    float* u_sh = sm;                      // [512][US]: 64 gate rows (local r = g*16+uu)
    float* h_st = u_sh + Hd * US;          // [512][8]:  this bg's h, dense
    float* part = h_st + Hd * 8;           // [16][64*PS2]: per-warp partials
    __shared__ unsigned long long s_base[NCTR2];

    const int tid  = threadIdx.x;
    const int blk  = blockIdx.x;
    const int BG   = blk >> 5;             // batch group 0..3 (batches 8*BG..8*BG+8)
    const int RG   = blk & 31;             // unit group 0..31 (units 16*RG..16*RG+16)
    const int lane = tid & 31;

    if (tid < NCTR2) {
        unsigned long long v = g_ctr[tid * 16];   // same-run extras <= 2 < PER_RUN
        s_base[tid] = (v / PER_RUN) * PER_RUN;
    }

    // ---------------- prologue: weights (64 rows x 512 k, transposed) -----------
    for (int idx = tid; idx < 64 * Hd; idx += NTHR) {
        int r = idx >> 9;                  // local row 0..63  (g = r>>4, uu = r&15)
        int k = idx & (Hd - 1);
        int R = ((r >> 4) << 9) + RG * 16 + (r & 15);
        u_sh[k * US + r] = u[(size_t)R * Hd + k];
    }

    const int uu = tid & 15;               // cell-thread coords (tid < 128)
    const int bb = tid >> 4;               // batch 0..7 within group
    float c_reg = 0.0f, br0 = 0, br1 = 0, br2 = 0, br3 = 0;
    if (tid < 128) {
        int b  = BG * 8 + bb;
        int jj = RG * 16 + uu;
        c_reg = c0[(size_t)b * Hd + jj];
        br0 = __ldg(&ub[0 * Hd + jj]);
        br1 = __ldg(&ub[1 * Hd + jj]);
        br2 = __ldg(&ub[2 * Hd + jj]);
        br3 = __ldg(&ub[3 * Hd + jj]);
        g_hbuf2[0][BG][jj][bb] = h0[(size_t)b * Hd + jj];
    }
    __syncthreads();                       // h0 stores + s_base visible
    if (tid == 0) red_add_release_u64(&g_ctr[(BG * 16 + (RG >> 1)) * 16]);

    // GEMM tiling: 16 warps = 16 k-slices of 32; lane = bt*16 + rt
    const int ks = tid >> 5;
    const int rt = lane & 15;              // rows    4*rt..4*rt+4
    const int bt = lane >> 4;              // batches 4*bt..4*bt+4 (2 f32x2 pairs)
    const int k0 = ks * KCH;

    const unsigned long long* my_ctr = &g_ctr[(BG * 16 + ks) * 16];
    unsigned long long target = s_base[BG * 16 + ks] + 2ull;

    const float* hP = h_st + (size_t)k0 * 8 + bt * 4;
    const float* uP = u_sh + (size_t)k0 * US + rt * 4;

    const size_t S = (size_t)Bz * Tt * Hd;

    for (int t = 0; t < Tt; t++) {
        const int p = t & 1;

        // wx prefetch (cell threads), overlaps the wait below
        float wr0 = 0, wr1 = 0, wr2 = 0, wr3 = 0;
        if (tid < 128) {
            const float* wp = wx + ((size_t)(BG * 8 + bb) * Tt + t) * G4 + RG * 16 + uu;
            wr0 = __ldg(wp + 0 * Hd);
            wr1 = __ldg(wp + 1 * Hd);
            wr2 = __ldg(wp + 2 * Hd);
            wr3 = __ldg(wp + 3 * Hd);
        }

        // ---- per-warp wait: only THIS warp's 2 producer blocks ----
        for (;;) {
            unsigned long long v = ld_acquire_u64(my_ctr);
            if ((long long)(v - target) >= 0) break;
        }
        target += 2ull;

        // ---- per-warp h chunk copy: dense 1KB (32 k x 8 batches) ----
        {
            const unsigned long long* src =
                reinterpret_cast<const unsigned long long*>(&g_hbuf2[p][BG][k0][0]);
            unsigned long long* dst =
                reinterpret_cast<unsigned long long*>(h_st + k0 * 8);
            #pragma unroll
            for (int i = 0; i < 4; i++) {
                unsigned long long v;
                asm volatile("ld.global.cg.b64 %0, [%1];" : "=l"(v)
                             : "l"(src + lane + 32 * i) : "memory");
                dst[lane + 32 * i] = v;
            }
        }
        __syncwarp();

        // ---- GEMM: per k: 2 LDS.128 + 4 DUP2 + 8 FFMA2 ----
        unsigned long long a00 = 0, a01 = 0, a10 = 0, a11 = 0;
        unsigned long long a20 = 0, a21 = 0, a30 = 0, a31 = 0;
        #pragma unroll 8
        for (int k = 0; k < KCH; k++) {
            ulonglong2 hp = *reinterpret_cast<const ulonglong2*>(hP + k * 8);
            float4     uv = *reinterpret_cast<const float4*>(uP + k * US);
            unsigned long long u0, u1, u2, u3;
            DUP2(u0, uv.x); DUP2(u1, uv.y); DUP2(u2, uv.z); DUP2(u3, uv.w);
            FFMA2(a00, hp.x, u0); FFMA2(a01, hp.y, u0);
            FFMA2(a10, hp.x, u1); FFMA2(a11, hp.y, u1);
            FFMA2(a20, hp.x, u2); FFMA2(a21, hp.y, u2);
            FFMA2(a30, hp.x, u3); FFMA2(a31, hp.y, u3);
        }
        {
            // part[ks][r][b]: r stride PS2(=14, even -> u64 aligned)
            unsigned long long* pp = reinterpret_cast<unsigned long long*>(
                part + ks * (64 * PS2) + (rt * 4) * PS2 + bt * 4);
            pp[0]              = a00;  pp[1]              = a01;
            pp[PS2 / 2]        = a10;  pp[PS2 / 2 + 1]    = a11;
            pp[PS2]            = a20;  pp[PS2 + 1]        = a21;
            pp[3 * PS2 / 2]    = a30;  pp[3 * PS2 / 2 + 1] = a31;
        }
        __syncthreads();                   // all 16 partial sets in smem

        // ---- fused reduce + LSTM cell (threads 0..127) ----
        float h, c, it, ft, gt, ot;
        if (tid < 128) {
            float s0, s1, s2, s3;
            {
                const float* q0 = part + uu * PS2 + bb;   // gate g adds g*16*PS2
                #define RED(g, bias, wxr, dst)                                    \
                {   const float* q = q0 + (g) * 16 * PS2;                          \
                    float t0 = q[0  * 64 * PS2] + q[1  * 64 * PS2];                \
                    float t1 = q[2  * 64 * PS2] + q[3  * 64 * PS2];                \
                    float t2 = q[4  * 64 * PS2] + q[5  * 64 * PS2];                \
                    float t3 = q[6  * 64 * PS2] + q[7  * 64 * PS2];                \
                    float t4 = q[8  * 64 * PS2] + q[9  * 64 * PS2];                \
                    float t5 = q[10 * 64 * PS2] + q[11 * 64 * PS2];                \
                    float t6 = q[12 * 64 * PS2] + q[13 * 64 * PS2];                \
                    float t7 = q[14 * 64 * PS2] + q[15 * 64 * PS2];                \
                    dst = (wxr + bias) +                                           \
                          (((t0 + t1) + (t2 + t3)) + ((t4 + t5) + (t6 + t7))); }
                RED(0, br0, wr0, s0)
                RED(1, br1, wr1, s1)
                RED(2, br2, wr2, s2)
                RED(3, br3, wr3, s3)
                #undef RED
            }
            it = sigf(s0);
            ft = sigf(s1);
            gt = tanhf_fast(s2);
            ot = sigf(s3);
            c  = ft * c_reg + it * gt;
            h  = ot * tanhf_fast(c);
            c_reg = c;
            g_hbuf2[p ^ 1][BG][RG * 16 + uu][bb] = h;  // weak; bar + release orders it
        }
        __syncthreads();
        if (tid == 0) red_add_release_u64(&g_ctr[(BG * 16 + (RG >> 1)) * 16]);

        if (tid < 128) {                   // outputs off the critical path
            size_t base = ((size_t)(BG * 8 + bb) * Tt + t) * Hd + RG * 16 + uu;
            out[base]         = h;
            out[S + base]     = c;
            out[2 * S + base] = it;
            out[3 * S + base] = ft;
            out[4 * S + base] = gt;
            out[5 * S + base] = ot;
        }
    }
}

extern "C" void kernel_launch(void* const* d_in, const int* in_sizes, int n_in,
                              void* d_out, int out_size) {
    const float* wx = (const float*)d_in[0];
    const float* u  = (const float*)d_in[1];
    const float* ub = (const float*)d_in[2];
    const float* h0 = (const float*)d_in[3];
    const float* c0 = (const float*)d_in[4];
    float* out = (float*)d_out;

    size_t smem = (size_t)(Hd * US + Hd * 8 + NW * 64 * PS2) * sizeof(float); // 212992 B
    cudaFuncSetAttribute(lstm_persistent,
                         cudaFuncAttributeMaxDynamicSharedMemorySize, (int)smem);
    lstm_persistent<<<NBLK, NTHR, smem>>>(wx, u, ub, h0, c0, out);
}